// round 7
// baseline (speedup 1.0000x reference)
#include <cuda_runtime.h>
#include <cstdint>

#define MAX_NODES 100000
#define MAX_EDGES 1600000

// ---------------- scratch (device globals; no allocation) ----------------
__device__ float g_agg[(size_t)MAX_NODES * 128];
__device__ float g_h  [(size_t)MAX_NODES * 128];
__device__ float g_z  [(size_t)MAX_NODES * 64];
__device__ int   g_deg[2 * MAX_NODES];   // [0..M): out-deg(src), [MAX_NODES..): in-deg(dst)
__device__ float g_ns[MAX_NODES];
__device__ float g_nd[MAX_NODES];
__device__ int   g_off[MAX_NODES];
__device__ int   g_cursor[MAX_NODES];
__device__ int   g_bsum[1024];
__device__ int   g_csrc[MAX_EDGES];

// ---------------- degrees ----------------
__global__ void deg_kernel(const int* __restrict__ src, const int* __restrict__ dst, int nE) {
    int e = blockIdx.x * blockDim.x + threadIdx.x;
    if (e < nE) {
        atomicAdd(&g_deg[src[e]], 1);
        atomicAdd(&g_deg[MAX_NODES + dst[e]], 1);
    }
}

// ---------------- per-1024 scan of in-degree + norms ----------------
__global__ void scan_blocks_norm(int n) {
    __shared__ int s[1024];
    int i = blockIdx.x * 1024 + threadIdx.x;
    int v = (i < n) ? g_deg[MAX_NODES + i] : 0;
    s[threadIdx.x] = v;
    __syncthreads();
#pragma unroll
    for (int o = 1; o < 1024; o <<= 1) {
        int t = (threadIdx.x >= o) ? s[threadIdx.x - o] : 0;
        __syncthreads();
        s[threadIdx.x] += t;
        __syncthreads();
    }
    if (i < n) {
        g_off[i] = s[threadIdx.x] - v;   // exclusive within block
        g_ns[i] = rsqrtf(fmaxf((float)g_deg[i], 1.0f));
        g_nd[i] = rsqrtf(fmaxf((float)v, 1.0f));
    }
    if (threadIdx.x == 1023) g_bsum[blockIdx.x] = s[1023];
}

// ---------------- add block prefix (block-sum scan inlined) ----------------
__global__ void scan_add2(int n, int nb) {
    __shared__ int sb[128];
    int t = threadIdx.x;
    if (t < 128) sb[t] = (t < nb) ? g_bsum[t] : 0;
    __syncthreads();
#pragma unroll
    for (int o = 1; o < 128; o <<= 1) {
        int v = (t < 128 && t >= o) ? sb[t - o] : 0;
        __syncthreads();
        if (t < 128) sb[t] += v;
        __syncthreads();
    }
    int i = blockIdx.x * blockDim.x + t;
    if (i < n) {
        int b = i >> 10;
        int o = g_off[i] + (b > 0 ? sb[b - 1] : 0);
        g_off[i] = o;
        g_cursor[i] = o;
    }
}

__global__ void build_csr(const int* __restrict__ src, const int* __restrict__ dst, int nE) {
    int e = blockIdx.x * blockDim.x + threadIdx.x;
    if (e < nE) {
        int p = atomicAdd(&g_cursor[dst[e]], 1);
        g_csrc[p] = src[e];
    }
}

// ---------------- pull aggregation ----------------
// SCALE: multiply gathered rows by ns[s] (layer 0 only; later layers have ns folded
// into the producing GEMM's epilogue).
template <bool SCALE>
__global__ void pull128(const float* __restrict__ X, float* __restrict__ agg, int M, int nE) {
    int t = blockIdx.x * blockDim.x + threadIdx.x;
    int node = t >> 5;
    int lane = t & 31;
    if (node >= M) return;
    int beg = __ldg(&g_off[node]);
    int end = (node + 1 < M) ? __ldg(&g_off[node + 1]) : nE;
    float4 acc = make_float4(0.f, 0.f, 0.f, 0.f);
    const float4* X4 = (const float4*)X;
#pragma unroll 2
    for (int e = beg; e < end; e++) {
        int s = __ldg(&g_csrc[e]);
        float4 v = __ldg(X4 + (size_t)s * 32 + lane);
        if (SCALE) {
            float w = __ldg(&g_ns[s]);
            acc.x += w * v.x; acc.y += w * v.y; acc.z += w * v.z; acc.w += w * v.w;
        } else {
            acc.x += v.x; acc.y += v.y; acc.z += v.z; acc.w += v.w;
        }
    }
    float nd = __ldg(&g_nd[node]);
    acc.x *= nd; acc.y *= nd; acc.z *= nd; acc.w *= nd;
    ((float4*)agg)[(size_t)node * 32 + lane] = acc;
}

// final layer: Z already carries ns; out = acc*nd + b2
__global__ void pull64_final(const float* __restrict__ Z, const float* __restrict__ b2,
                             float* __restrict__ out, int M, int nE) {
    int t = blockIdx.x * blockDim.x + threadIdx.x;
    int node = t >> 4;
    int l = t & 15;
    if (node >= M) return;
    int beg = __ldg(&g_off[node]);
    int end = (node + 1 < M) ? __ldg(&g_off[node + 1]) : nE;
    float4 acc = make_float4(0.f, 0.f, 0.f, 0.f);
    const float4* Z4 = (const float4*)Z;
#pragma unroll 2
    for (int e = beg; e < end; e++) {
        int s = __ldg(&g_csrc[e]);
        float4 v = __ldg(Z4 + (size_t)s * 16 + l);
        acc.x += v.x; acc.y += v.y; acc.z += v.z; acc.w += v.w;
    }
    float nd = __ldg(&g_nd[node]);
    float4 b = __ldg((const float4*)b2 + l);
    acc.x = acc.x * nd + b.x;
    acc.y = acc.y * nd + b.y;
    acc.z = acc.z * nd + b.z;
    acc.w = acc.w * nd + b.w;
    ((float4*)out)[(size_t)node * 16 + l] = acc;
}

// ---------------- tf32 helpers ----------------
__device__ __forceinline__ float f2tf32(float x) {
    uint32_t r;
    asm("cvt.rna.tf32.f32 %0, %1;" : "=r"(r) : "f"(x));
    return __uint_as_float(r);
}

__device__ __forceinline__ void mma_tf32(float* d, const uint32_t* a, const uint32_t* b) {
    asm volatile(
        "mma.sync.aligned.m16n8k8.row.col.f32.tf32.tf32.f32 "
        "{%0,%1,%2,%3}, {%4,%5,%6,%7}, {%8,%9}, {%0,%1,%2,%3};"
        : "+f"(d[0]), "+f"(d[1]), "+f"(d[2]), "+f"(d[3])
        : "r"(a[0]), "r"(a[1]), "r"(a[2]), "r"(a[3]), "r"(b[0]), "r"(b[1]));
}

// ---------------- TF32 GEMM v2: pipelined, double-buffered, 3xTF32 split ----------------
// out[M,BN] = epi(A[M,128] @ W[128,BN] (+bias, relu)) (* ns[row] if SCALE_NS)
// BM=128, BK=8, 256 threads, warps 4(m) x 2(n), warp tile 32 x BN/2, mma m16n8k8.
template <int BN, bool RELU, bool SCALE_NS>
__global__ void __launch_bounds__(256) gemm_v2(
    const float* __restrict__ A, const float* __restrict__ W,
    const float* __restrict__ bias, float* __restrict__ out, int M) {

    constexpr int AP = 9;            // A smem row stride (conflict-free: 9q mod 32 distinct)
    constexpr int BNP = BN + 8;      // B smem row stride (8*k term spreads banks)
    constexpr int NT = BN / 16;      // n-tiles per warp
    constexpr int NCH = NT / 4;

    __shared__ float Ah[2][128 * AP], Al[2][128 * AP];
    __shared__ float Bh[2][8 * BNP], Bl[2][8 * BNP];

    const int tid = threadIdx.x;
    const int lane = tid & 31;
    const int warp = tid >> 5;
    const int wm = warp & 3;
    const int wn = (warp >> 2) * (BN / 2);
    const int m0 = blockIdx.x * 128;

    // fill-phase coordinates
    const int a_rid = tid >> 1;          // row within block tile (0..127)
    const int a_c2 = tid & 1;            // which float4 within BK=8
    const int a_row = m0 + a_rid;
    const int b_kr = (BN == 128) ? (tid >> 5) : (tid >> 4);
    const int b_nc = (BN == 128) ? (tid & 31) : (tid & 15);
    const bool b_act = (BN == 128) || (tid < 128);

    float acc[2][NT][4];
#pragma unroll
    for (int mt = 0; mt < 2; mt++)
#pragma unroll
        for (int nt = 0; nt < NT; nt++)
#pragma unroll
            for (int i = 0; i < 4; i++) acc[mt][nt][i] = 0.0f;

    float4 va = make_float4(0.f, 0.f, 0.f, 0.f);
    float4 vb = make_float4(0.f, 0.f, 0.f, 0.f);
    if (a_row < M) va = *((const float4*)(A + (size_t)a_row * 128 + a_c2 * 4));
    if (b_act)     vb = *((const float4*)(W + (size_t)b_kr * BN + b_nc * 4));

    // STS with hi/lo split; A col swizzle: c ^= (rid>>3)&1 ; B col swizzle: n ^= (n>>3)&15
    auto stsA = [&](int buf, float4 v) {
        const float* p = reinterpret_cast<const float*>(&v);
        int swz = (a_rid >> 3) & 1;
#pragma unroll
        for (int i = 0; i < 4; i++) {
            float x = p[i];
            float h = f2tf32(x);
            float l = f2tf32(x - h);
            int c = (a_c2 * 4 + i) ^ swz;
            Ah[buf][a_rid * AP + c] = h;
            Al[buf][a_rid * AP + c] = l;
        }
    };
    auto stsB = [&](int buf, float4 v) {
        if (!b_act) return;
        const float* p = reinterpret_cast<const float*>(&v);
#pragma unroll
        for (int i = 0; i < 4; i++) {
            float x = p[i];
            float h = f2tf32(x);
            float l = f2tf32(x - h);
            int n = b_nc * 4 + i;
            int nsw = n ^ ((n >> 3) & 15);
            Bh[buf][b_kr * BNP + nsw] = h;
            Bl[buf][b_kr * BNP + nsw] = l;
        }
    };

    stsA(0, va);
    stsB(0, vb);
    __syncthreads();

    const int c0 = lane & 3;     // k within frag
    const int q = lane >> 2;     // row/col group

    for (int kt = 0; kt < 16; kt++) {
        int buf = kt & 1;
        if (kt < 15) {
            int kk = (kt + 1) * 8;
            va = make_float4(0.f, 0.f, 0.f, 0.f);
            if (a_row < M) va = *((const float4*)(A + (size_t)a_row * 128 + kk + a_c2 * 4));
            if (b_act) vb = *((const float4*)(W + (size_t)(kk + b_kr) * BN + b_nc * 4));
        }

        // A fragments: hoisted, loaded once per ktile
        uint32_t ah[2][4], al[2][4];
#pragma unroll
        for (int mt = 0; mt < 2; mt++) {
            int r0 = wm * 32 + mt * 16 + q;
            int r8 = r0 + 8;
            int s0 = (r0 >> 3) & 1, s8 = (r8 >> 3) & 1;
            ah[mt][0] = __float_as_uint(Ah[buf][r0 * AP + (c0 ^ s0)]);
            ah[mt][1] = __float_as_uint(Ah[buf][r8 * AP + (c0 ^ s8)]);
            ah[mt][2] = __float_as_uint(Ah[buf][r0 * AP + ((c0 + 4) ^ s0)]);
            ah[mt][3] = __float_as_uint(Ah[buf][r8 * AP + ((c0 + 4) ^ s8)]);
            al[mt][0] = __float_as_uint(Al[buf][r0 * AP + (c0 ^ s0)]);
            al[mt][1] = __float_as_uint(Al[buf][r8 * AP + (c0 ^ s8)]);
            al[mt][2] = __float_as_uint(Al[buf][r0 * AP + ((c0 + 4) ^ s0)]);
            al[mt][3] = __float_as_uint(Al[buf][r8 * AP + ((c0 + 4) ^ s8)]);
        }

#pragma unroll
        for (int nc = 0; nc < NCH; nc++) {
#pragma unroll
            for (int j = 0; j < 4; j++) {
                int nt = nc * 4 + j;
                int col = wn + nt * 8 + q;
                int csw = col ^ ((col >> 3) & 15);
                uint32_t bh[2], bl[2];
                bh[0] = __float_as_uint(Bh[buf][c0 * BNP + csw]);
                bh[1] = __float_as_uint(Bh[buf][(c0 + 4) * BNP + csw]);
                bl[0] = __float_as_uint(Bl[buf][c0 * BNP + csw]);
                bl[1] = __float_as_uint(Bl[buf][(c0 + 4) * BNP + csw]);
#pragma unroll
                for (int mt = 0; mt < 2; mt++) {
                    mma_tf32(acc[mt][nt], ah[mt], bh);
                    mma_tf32(acc[mt][nt], ah[mt], bl);
                    mma_tf32(acc[mt][nt], al[mt], bh);
                }
            }
        }

        if (kt < 15) {
            stsA(buf ^ 1, va);
            stsB(buf ^ 1, vb);
        }
        __syncthreads();
    }

    // ---- epilogue ----
#pragma unroll
    for (int mt = 0; mt < 2; mt++) {
        const int row0 = m0 + wm * 32 + mt * 16 + q;
#pragma unroll
        for (int nt = 0; nt < NT; nt++) {
            const int col = wn + nt * 8 + 2 * c0;
#pragma unroll
            for (int h = 0; h < 2; h++) {
                int row = row0 + 8 * h;
                if (row < M) {
                    float2 v;
                    v.x = acc[mt][nt][2 * h + 0];
                    v.y = acc[mt][nt][2 * h + 1];
                    if (RELU) {
                        v.x = fmaxf(v.x + __ldg(&bias[col + 0]), 0.f);
                        v.y = fmaxf(v.y + __ldg(&bias[col + 1]), 0.f);
                    }
                    if (SCALE_NS) {
                        float ns = __ldg(&g_ns[row]);
                        v.x *= ns; v.y *= ns;
                    }
                    *((float2*)(out + (size_t)row * BN + col)) = v;
                }
            }
        }
    }
}

// ---------------- launch ----------------
extern "C" void kernel_launch(void* const* d_in, const int* in_sizes, int n_in,
                              void* d_out, int out_size) {
    const float* feat = (const float*)d_in[0];
    const int*   src  = (const int*)d_in[1];
    const int*   dst  = (const int*)d_in[2];
    const float* W0   = (const float*)d_in[3];
    const float* b0   = (const float*)d_in[4];
    const float* W1   = (const float*)d_in[5];
    const float* b1   = (const float*)d_in[6];
    const float* W2   = (const float*)d_in[7];
    const float* b2   = (const float*)d_in[8];

    const int nE = in_sizes[1];
    const int M  = in_sizes[0] / 128;

    float* out = (float*)d_out;

    void *p_agg, *p_h, *p_z, *p_deg;
    cudaGetSymbolAddress(&p_agg, g_agg);
    cudaGetSymbolAddress(&p_h,   g_h);
    cudaGetSymbolAddress(&p_z,   g_z);
    cudaGetSymbolAddress(&p_deg, g_deg);

    // 1: zero degrees (single memset over both halves)
    cudaMemsetAsync(p_deg, 0, (size_t)2 * MAX_NODES * sizeof(int), 0);
    // 2: degrees
    deg_kernel<<<(nE + 255) / 256, 256>>>(src, dst, nE);
    // 3: per-block scan + norms
    const int nb = (M + 1023) / 1024;
    scan_blocks_norm<<<nb, 1024>>>(M);
    // 4: block-prefix add (inline block-sum scan)
    scan_add2<<<(M + 255) / 256, 256>>>(M, nb);
    // 5: CSR build
    build_csr<<<(nE + 255) / 256, 256>>>(src, dst, nE);

    const unsigned pb128 = (unsigned)(((size_t)M * 32 + 255) / 256);
    const unsigned pb64  = (unsigned)(((size_t)M * 16 + 255) / 256);
    const unsigned gblocks = (unsigned)((M + 127) / 128);

    // Layer 0: pull (scaled by ns) -> GEMM (relu+bias, epilogue * ns for next layer)
    pull128<true><<<pb128, 256>>>(feat, (float*)p_agg, M, nE);                        // 6th launch (profiled)
    gemm_v2<128, true, true><<<gblocks, 256>>>((const float*)p_agg, W0, b0, (float*)p_h, M);

    // Layer 1: pull (ns already folded in) -> GEMM (relu+bias, NO ns: output feeds gemm2)
    pull128<false><<<pb128, 256>>>((const float*)p_h, (float*)p_agg, M, nE);
    gemm_v2<128, true, false><<<gblocks, 256>>>((const float*)p_agg, W1, b1, (float*)p_h, M);

    // Layer 2: GEMM first (128->64, epilogue * ns), then 64-wide pull + final epilogue
    gemm_v2<64, false, true><<<gblocks, 256>>>((const float*)p_h, W2, b2, (float*)p_z, M);
    pull64_final<<<pb64, 256>>>((const float*)p_z, b2, out, M, nE);
}